// round 5
// baseline (speedup 1.0000x reference)
#include <cuda_runtime.h>
#include <cstdint>

#define BB 131072
#define CC 256
#define DD 64
#define NSTEP 8
#define DTB 0.15f
#define EPSV 1e-4f
#define THREADS 256

typedef unsigned long long u64;

// ---- f32x2 packed helpers (SASS FFMA2; PTX-only). Carrier type = u64 for "l". ----
__device__ __forceinline__ u64 ffma2(u64 a, u64 b, u64 c) {
    u64 d;
    asm("fma.rn.f32x2 %0, %1, %2, %3;" : "=l"(d) : "l"(a), "l"(b), "l"(c));
    return d;
}
__device__ __forceinline__ u64 pack2(float lo, float hi) {
    u64 d;
    asm("mov.b64 %0, {%1, %2};" : "=l"(d) : "f"(lo), "f"(hi));
    return d;
}
__device__ __forceinline__ void unpack2(u64 d, float& lo, float& hi) {
    asm("mov.b64 {%0, %1}, %2;" : "=f"(lo), "=f"(hi) : "l"(d));
}

// Dynamic SMEM layout:
//   [0 .. 8192)  u64: centers packed f32x2, row-major [256][32]  (64 KB)
//   then 256 floats cn2, 256 floats mu
#define SMEM_BYTES (65536 + 1024 + 1024)

__global__ void __launch_bounds__(THREADS, 1) pm_field_kernel(
    const float* __restrict__ z_in,
    const float* __restrict__ centers,
    const float* __restrict__ mus,
    float* __restrict__ out)
{
    extern __shared__ u64 smem_d[];
    u64*   sc   = smem_d;                       // [256][32] packed center rows
    float* scn2 = (float*)(smem_d + 8192);      // [256]
    float* smu  = scn2 + CC;                    // [256]

    const int tid = threadIdx.x;

    // Stage centers (packed), cn2, mu into SMEM.
    {
        const u64* cg = (const u64*)centers;    // rows are 256B, 8B-aligned
        for (int i = tid; i < CC * (DD / 2); i += THREADS)
            sc[i] = cg[i];
        for (int c = tid; c < CC; c += THREADS) {
            float s = 0.f;
            const float* crow = centers + c * DD;
            #pragma unroll
            for (int d = 0; d < DD; d++) s = fmaf(crow[d], crow[d], s);
            scn2[c] = s;
            smu[c]  = mus[c];
        }
    }
    __syncthreads();

    // One thread = one row, resident in registers for all 8 steps.
    const long long row = (long long)blockIdx.x * THREADS + tid;   // 512*256 = 131072 exact
    const u64* zg = (const u64*)(z_in + row * DD);

    u64 zr[DD / 2];
    #pragma unroll
    for (int j = 0; j < DD / 2; j++) zr[j] = zg[j];

    const u64 zero2 = 0ull;

    for (int step = 0; step < NSTEP; step++) {
        // zz = |z|^2
        u64 za[4] = {zero2, zero2, zero2, zero2};
        #pragma unroll
        for (int j = 0; j < DD / 2; j++) za[j & 3] = ffma2(zr[j], zr[j], za[j & 3]);
        float zz;
        {
            float a0, a1, b0, b1, c0, c1, d0, d1;
            unpack2(za[0], a0, a1); unpack2(za[1], b0, b1);
            unpack2(za[2], c0, c1); unpack2(za[3], d0, d1);
            zz = ((a0 + a1) + (b0 + b1)) + ((c0 + c1) + (d0 + d1));
        }

        float n = 1.0f, sumw = 0.0f;
        u64 ga[DD / 2];
        #pragma unroll
        for (int j = 0; j < DD / 2; j++) ga[j] = zero2;

        for (int c = 0; c < CC; c++) {
            // center row -> registers (broadcast LDS.128, conflict-free)
            u64 cr[DD / 2];
            const ulonglong2* crow = (const ulonglong2*)(sc + c * (DD / 2));
            #pragma unroll
            for (int j = 0; j < DD / 4; j++) {
                ulonglong2 v = crow[j];
                cr[2 * j]     = v.x;
                cr[2 * j + 1] = v.y;
            }

            // dot(z, c) with 4 packed accumulators
            u64 da[4] = {zero2, zero2, zero2, zero2};
            #pragma unroll
            for (int j = 0; j < DD / 2; j++) da[j & 3] = ffma2(zr[j], cr[j], da[j & 3]);
            float dot;
            {
                float a0, a1, b0, b1, c0, c1, d0, d1;
                unpack2(da[0], a0, a1); unpack2(da[1], b0, b1);
                unpack2(da[2], c0, c1); unpack2(da[3], d0, d1);
                dot = ((a0 + a1) + (b0 + b1)) + ((c0 + c1) + (d0 + d1));
            }

            float r2   = fmaxf(zz + scn2[c] - 2.0f * dot, 0.0f) + EPSV;
            float invr = rsqrtf(r2);
            float miv  = smu[c] * invr;
            n += miv;
            float w = miv * invr * invr;   // mu / r^3
            sumw += w;

            u64 w2 = pack2(w, w);
            #pragma unroll
            for (int j = 0; j < DD / 2; j++) ga[j] = ffma2(w2, cr[j], ga[j]);
        }

        const float coef = DTB / n;
        #pragma unroll
        for (int j = 0; j < DD / 2; j++) {
            float zlo, zhi, glo, ghi;
            unpack2(zr[j], zlo, zhi);
            unpack2(ga[j], glo, ghi);
            zlo = fminf(fmaxf(fmaf(coef, glo - zlo * sumw, zlo), -3.0f), 3.0f);
            zhi = fminf(fmaxf(fmaf(coef, ghi - zhi * sumw, zhi), -3.0f), 3.0f);
            zr[j] = pack2(zlo, zhi);
        }
    }

    u64* og = (u64*)(out + row * DD);
    #pragma unroll
    for (int j = 0; j < DD / 2; j++) og[j] = zr[j];
}

extern "C" void kernel_launch(void* const* d_in, const int* in_sizes, int n_in,
                              void* d_out, int out_size) {
    (void)in_sizes; (void)n_in; (void)out_size;
    const float* z       = (const float*)d_in[0];
    const float* centers = (const float*)d_in[1];
    const float* mus     = (const float*)d_in[2];
    float* out           = (float*)d_out;

    static bool attr_set = false;
    if (!attr_set) {
        cudaFuncSetAttribute(pm_field_kernel,
                             cudaFuncAttributeMaxDynamicSharedMemorySize, SMEM_BYTES);
        attr_set = true;
    }

    const int n_blocks = BB / THREADS;   // 512
    pm_field_kernel<<<n_blocks, THREADS, SMEM_BYTES>>>(z, centers, mus, out);
}

// round 7
// speedup vs baseline: 4.3643x; 4.3643x over previous
#include <cuda_runtime.h>
#include <cuda_bf16.h>
#include <cstdint>

#define BB 131072
#define CC 256
#define DD 64
#define NSTEP 8
#define DTB 0.15f
#define EPSV 1e-4f
#define ROWS 128
#define THREADS 256
#define NBLK (BB / ROWS)          // 1024

// ---------------- SMEM layout ----------------
// B1f: uint2[4 kt][32 nt][32 lane]   (GEMM1 B fragments)   32768 B
// B2f: uint2[16 kt][8 nt][32 lane]   (GEMM2 B fragments)   32768 B
// cs : float[256*64] staged centers                        65536 B
// sqm: float2[256]  (cn2, mu)                               2048 B
#define SM_B1F 0
#define SM_B2F 32768
#define SM_CS  65536
#define SM_QM  131072
#define SM_TOTAL 133120

// bf16x2 pack: lo = a (lower/even col), hi = b
static __device__ __forceinline__ uint32_t pack_bf16x2(float a, float b) {
    uint32_t r;
    asm("cvt.rn.bf16x2.f32 %0, %1, %2;" : "=r"(r) : "f"(b), "f"(a));
    return r;
}

// m16n8k16 row.col f32.bf16.bf16.f32 — portable tensor-core path (plain sm_103 OK)
static __device__ __forceinline__ void mma16816(
    float* c, uint32_t a0, uint32_t a1, uint32_t a2, uint32_t a3,
    uint32_t b0, uint32_t b1)
{
    asm volatile(
        "mma.sync.aligned.m16n8k16.row.col.f32.bf16.bf16.f32 "
        "{%0,%1,%2,%3}, {%4,%5,%6,%7}, {%8,%9}, {%0,%1,%2,%3};"
        : "+f"(c[0]), "+f"(c[1]), "+f"(c[2]), "+f"(c[3])
        : "r"(a0), "r"(a1), "r"(a2), "r"(a3), "r"(b0), "r"(b1));
}

__global__ void __launch_bounds__(THREADS, 1) pm_field_mma_kernel(
    const float* __restrict__ z_in,
    const float* __restrict__ centers,
    const float* __restrict__ mus,
    float* __restrict__ out)
{
    extern __shared__ char smem[];
    uint2*  B1f = (uint2*)(smem + SM_B1F);
    uint2*  B2f = (uint2*)(smem + SM_B2F);
    float*  cs  = (float*)(smem + SM_CS);
    float2* sqm = (float2*)(smem + SM_QM);

    const int tid  = threadIdx.x;
    const int wid  = tid >> 5;
    const int lane = tid & 31;
    const int m    = lane & 3;     // threadID_in_group (col quad)
    const int g    = lane >> 2;    // groupID (row)

    // ---- stage centers fp32 (coalesced) ----
    {
        const float4* src = (const float4*)centers;
        float4* dst = (float4*)cs;
        for (int i = tid; i < CC * DD / 4; i += THREADS) dst[i] = src[i];
    }
    __syncthreads();

    // ---- cn2 + mu ----
    {
        int c = tid;  // THREADS == CC
        float s = 0.f;
        const float* cr = cs + c * DD;
        #pragma unroll
        for (int d = 0; d < DD; d++) s = fmaf(cr[d], cr[d], s);
        sqm[c] = make_float2(s, mus[c]);
    }

    // ---- B fragments, lane-indexed (conflict-free LDS in mainloop) ----
    // GEMM1: B[k=d][n=c] = centers[c][d]  (col-major frag == centers rows)
    #pragma unroll
    for (int kt = 0; kt < 4; kt++)
        for (int nt = 0; nt < 32; nt++) {
            const float* p = cs + (8 * nt + g) * DD + 16 * kt + 2 * m;
            float2 f0 = *(const float2*)p;
            float2 f1 = *(const float2*)(p + 8);
            B1f[(kt * 32 + nt) * 32 + lane] =
                make_uint2(pack_bf16x2(f0.x, f0.y), pack_bf16x2(f1.x, f1.y));
        }
    // GEMM2: B[k=c][n=d] = centers[c][d]
    #pragma unroll
    for (int kt = 0; kt < 16; kt++)
        for (int nt = 0; nt < 8; nt++) {
            int c0 = 16 * kt + 2 * m, d = 8 * nt + g;
            uint32_t b0 = pack_bf16x2(cs[c0 * DD + d],       cs[(c0 + 1) * DD + d]);
            uint32_t b1 = pack_bf16x2(cs[(c0 + 8) * DD + d], cs[(c0 + 9) * DD + d]);
            B2f[(kt * 8 + nt) * 32 + lane] = make_uint2(b0, b1);
        }
    __syncthreads();
    // ======== from here on: ZERO block-level syncs — warps fully autonomous ======

    // ---- z: warp owns 16 rows; thread owns rows r0=g, r1=g+8 and 16 cols each
    //      col(j) = 8*(j>>1) + 2*m + (j&1) ----
    const int r0 = blockIdx.x * ROWS + wid * 16 + g;
    float zr0[16], zr1[16];
    #pragma unroll
    for (int blk = 0; blk < 8; blk++) {
        float2 v0 = *(const float2*)(z_in + (size_t)r0 * DD + 8 * blk + 2 * m);
        float2 v1 = *(const float2*)(z_in + (size_t)(r0 + 8) * DD + 8 * blk + 2 * m);
        zr0[2 * blk] = v0.x; zr0[2 * blk + 1] = v0.y;
        zr1[2 * blk] = v1.x; zr1[2 * blk + 1] = v1.y;
    }

    for (int step = 0; step < NSTEP; step++) {
        // ---- zz per row (quad reduce) ----
        float s0 = 0.f, s1 = 0.f;
        #pragma unroll
        for (int j = 0; j < 16; j++) {
            s0 = fmaf(zr0[j], zr0[j], s0);
            s1 = fmaf(zr1[j], zr1[j], s1);
        }
        s0 += __shfl_xor_sync(0xFFFFFFFFu, s0, 1);
        s0 += __shfl_xor_sync(0xFFFFFFFFu, s0, 2);
        s1 += __shfl_xor_sync(0xFFFFFFFFu, s1, 1);
        s1 += __shfl_xor_sync(0xFFFFFFFFu, s1, 2);

        // ---- A fragments of GEMM1 from register z ----
        uint32_t af[4][4];
        #pragma unroll
        for (int kt = 0; kt < 4; kt++) {
            af[kt][0] = pack_bf16x2(zr0[4 * kt + 0], zr0[4 * kt + 1]);
            af[kt][1] = pack_bf16x2(zr1[4 * kt + 0], zr1[4 * kt + 1]);
            af[kt][2] = pack_bf16x2(zr0[4 * kt + 2], zr0[4 * kt + 3]);
            af[kt][3] = pack_bf16x2(zr1[4 * kt + 2], zr1[4 * kt + 3]);
        }

        uint32_t wa[16][4];                 // W fragments (A of GEMM2)
        float na0 = 0.f, na1 = 0.f, sw0 = 0.f, sw1 = 0.f;

        // ---- GEMM1 + epilogue in two n-halves (caps accumulator live range) ----
        #pragma unroll
        for (int h = 0; h < 2; h++) {
            float acc[16][4];
            #pragma unroll
            for (int i = 0; i < 16; i++)
                acc[i][0] = acc[i][1] = acc[i][2] = acc[i][3] = 0.f;

            #pragma unroll
            for (int kt = 0; kt < 4; kt++) {
                #pragma unroll
                for (int ntl = 0; ntl < 16; ntl++) {
                    uint2 b = B1f[(kt * 32 + 16 * h + ntl) * 32 + lane];
                    mma16816(acc[ntl], af[kt][0], af[kt][1], af[kt][2], af[kt][3],
                             b.x, b.y);
                }
            }

            // epilogue: w = mu/r^3 per fragment element; pack into GEMM2 A frags
            #pragma unroll
            for (int ntl = 0; ntl < 16; ntl++) {
                const int col0 = 8 * (16 * h + ntl) + 2 * m;
                float2 q0 = sqm[col0];
                float2 q1 = sqm[col0 + 1];

                float t00 = fmaxf(fmaf(-2.f, acc[ntl][0], s0 + q0.x), 0.f) + EPSV;
                float t01 = fmaxf(fmaf(-2.f, acc[ntl][1], s0 + q1.x), 0.f) + EPSV;
                float t10 = fmaxf(fmaf(-2.f, acc[ntl][2], s1 + q0.x), 0.f) + EPSV;
                float t11 = fmaxf(fmaf(-2.f, acc[ntl][3], s1 + q1.x), 0.f) + EPSV;
                float i00 = rsqrtf(t00), i01 = rsqrtf(t01);
                float i10 = rsqrtf(t10), i11 = rsqrtf(t11);
                float m00 = q0.y * i00, m01 = q1.y * i01;
                float m10 = q0.y * i10, m11 = q1.y * i11;
                na0 += m00 + m01;  na1 += m10 + m11;
                float w00 = m00 * i00 * i00, w01 = m01 * i01 * i01;
                float w10 = m10 * i10 * i10, w11 = m11 * i11 * i11;
                sw0 += w00 + w01;  sw1 += w10 + w11;

                const int KT = 8 * h + (ntl >> 1);
                if ((ntl & 1) == 0) {
                    wa[KT][0] = pack_bf16x2(w00, w01);
                    wa[KT][1] = pack_bf16x2(w10, w11);
                } else {
                    wa[KT][2] = pack_bf16x2(w00, w01);
                    wa[KT][3] = pack_bf16x2(w10, w11);
                }
            }
        }

        // ---- GEMM2: G = W @ centers ----
        float gacc[8][4];
        #pragma unroll
        for (int i = 0; i < 8; i++)
            gacc[i][0] = gacc[i][1] = gacc[i][2] = gacc[i][3] = 0.f;
        #pragma unroll
        for (int kt = 0; kt < 16; kt++) {
            #pragma unroll
            for (int nt = 0; nt < 8; nt++) {
                uint2 b = B2f[(kt * 8 + nt) * 32 + lane];
                mma16816(gacc[nt], wa[kt][0], wa[kt][1], wa[kt][2], wa[kt][3],
                         b.x, b.y);
            }
        }

        // ---- row reductions + update ----
        na0 += __shfl_xor_sync(0xFFFFFFFFu, na0, 1);
        na0 += __shfl_xor_sync(0xFFFFFFFFu, na0, 2);
        na1 += __shfl_xor_sync(0xFFFFFFFFu, na1, 1);
        na1 += __shfl_xor_sync(0xFFFFFFFFu, na1, 2);
        sw0 += __shfl_xor_sync(0xFFFFFFFFu, sw0, 1);
        sw0 += __shfl_xor_sync(0xFFFFFFFFu, sw0, 2);
        sw1 += __shfl_xor_sync(0xFFFFFFFFu, sw1, 1);
        sw1 += __shfl_xor_sync(0xFFFFFFFFu, sw1, 2);

        const float coef0 = DTB / (1.f + na0);
        const float coef1 = DTB / (1.f + na1);
        #pragma unroll
        for (int nt = 0; nt < 8; nt++) {
            float u;
            u = fmaf(coef0, fmaf(-sw0, zr0[2 * nt],     gacc[nt][0]), zr0[2 * nt]);
            zr0[2 * nt]     = fminf(fmaxf(u, -3.f), 3.f);
            u = fmaf(coef0, fmaf(-sw0, zr0[2 * nt + 1], gacc[nt][1]), zr0[2 * nt + 1]);
            zr0[2 * nt + 1] = fminf(fmaxf(u, -3.f), 3.f);
            u = fmaf(coef1, fmaf(-sw1, zr1[2 * nt],     gacc[nt][2]), zr1[2 * nt]);
            zr1[2 * nt]     = fminf(fmaxf(u, -3.f), 3.f);
            u = fmaf(coef1, fmaf(-sw1, zr1[2 * nt + 1], gacc[nt][3]), zr1[2 * nt + 1]);
            zr1[2 * nt + 1] = fminf(fmaxf(u, -3.f), 3.f);
        }
    }

    // ---- store ----
    #pragma unroll
    for (int blk = 0; blk < 8; blk++) {
        *(float2*)(out + (size_t)r0 * DD + 8 * blk + 2 * m) =
            make_float2(zr0[2 * blk], zr0[2 * blk + 1]);
        *(float2*)(out + (size_t)(r0 + 8) * DD + 8 * blk + 2 * m) =
            make_float2(zr1[2 * blk], zr1[2 * blk + 1]);
    }
}

extern "C" void kernel_launch(void* const* d_in, const int* in_sizes, int n_in,
                              void* d_out, int out_size) {
    (void)in_sizes; (void)n_in; (void)out_size;
    const float* z       = (const float*)d_in[0];
    const float* centers = (const float*)d_in[1];
    const float* mus     = (const float*)d_in[2];
    float* out           = (float*)d_out;

    static bool attr_set = false;
    if (!attr_set) {
        cudaFuncSetAttribute(pm_field_mma_kernel,
                             cudaFuncAttributeMaxDynamicSharedMemorySize, SM_TOTAL);
        attr_set = true;
    }
    pm_field_mma_kernel<<<NBLK, THREADS, SM_TOTAL>>>(z, centers, mus, out);
}

// round 8
// speedup vs baseline: 4.6087x; 1.0560x over previous
#include <cuda_runtime.h>
#include <cuda_bf16.h>
#include <cstdint>

#define BB 131072
#define CC 256
#define DD 64
#define NSTEP 8
#define DTB 0.15f
#define EPSV 1e-4f
#define ROWS 256                  // per CTA (8 warps x 32 rows)
#define THREADS 256
#define NBLK (BB / ROWS)          // 512

// ---------------- SMEM layout ----------------
#define SM_B1F 0                  // uint2[4 kt][32 nt][32 lane]  32768
#define SM_B2F 32768              // uint2[16 kt][8 nt][32 lane]  32768
#define SM_CS  65536              // float[256*64]                65536
#define SM_QM  131072             // float2[256] (cn2, mu)         2048
#define SM_TOTAL 133120

static __device__ __forceinline__ uint32_t pack_bf16x2(float a, float b) {
    uint32_t r;
    asm("cvt.rn.bf16x2.f32 %0, %1, %2;" : "=r"(r) : "f"(b), "f"(a));
    return r;
}
static __device__ __forceinline__ void mma16816(
    float* c, uint32_t a0, uint32_t a1, uint32_t a2, uint32_t a3,
    uint32_t b0, uint32_t b1)
{
    asm volatile(
        "mma.sync.aligned.m16n8k16.row.col.f32.bf16.bf16.f32 "
        "{%0,%1,%2,%3}, {%4,%5,%6,%7}, {%8,%9}, {%0,%1,%2,%3};"
        : "+f"(c[0]), "+f"(c[1]), "+f"(c[2]), "+f"(c[3])
        : "r"(a0), "r"(a1), "r"(a2), "r"(a3), "r"(b0), "r"(b1));
}
static __device__ __forceinline__ float qred(float v) {  // quad reduce (cols)
    v += __shfl_xor_sync(0xFFFFFFFFu, v, 1);
    v += __shfl_xor_sync(0xFFFFFFFFu, v, 2);
    return v;
}

__global__ void __launch_bounds__(THREADS, 1) pm_field_mma_kernel(
    const float* __restrict__ z_in,
    const float* __restrict__ centers,
    const float* __restrict__ mus,
    float* __restrict__ out)
{
    extern __shared__ char smem[];
    uint2*  B1f = (uint2*)(smem + SM_B1F);
    uint2*  B2f = (uint2*)(smem + SM_B2F);
    float*  cs  = (float*)(smem + SM_CS);
    float2* sqm = (float2*)(smem + SM_QM);

    const int tid  = threadIdx.x;
    const int wid  = tid >> 5;
    const int lane = tid & 31;
    const int m    = lane & 3;
    const int g    = lane >> 2;

    // ---- stage centers fp32 ----
    {
        const float4* src = (const float4*)centers;
        float4* dst = (float4*)cs;
        for (int i = tid; i < CC * DD / 4; i += THREADS) dst[i] = src[i];
    }
    __syncthreads();
    {
        int c = tid;  // THREADS == CC
        float s = 0.f;
        const float* cr = cs + c * DD;
        #pragma unroll
        for (int d = 0; d < DD; d++) s = fmaf(cr[d], cr[d], s);
        sqm[c] = make_float2(s, mus[c]);
    }
    // ---- B fragments (lane-indexed, conflict-free) ----
    #pragma unroll
    for (int kt = 0; kt < 4; kt++)
        for (int nt = 0; nt < 32; nt++) {
            const float* p = cs + (8 * nt + g) * DD + 16 * kt + 2 * m;
            float2 f0 = *(const float2*)p;
            float2 f1 = *(const float2*)(p + 8);
            B1f[(kt * 32 + nt) * 32 + lane] =
                make_uint2(pack_bf16x2(f0.x, f0.y), pack_bf16x2(f1.x, f1.y));
        }
    #pragma unroll
    for (int kt = 0; kt < 16; kt++)
        for (int nt = 0; nt < 8; nt++) {
            int c0 = 16 * kt + 2 * m, d = 8 * nt + g;
            uint32_t b0 = pack_bf16x2(cs[c0 * DD + d],       cs[(c0 + 1) * DD + d]);
            uint32_t b1 = pack_bf16x2(cs[(c0 + 8) * DD + d], cs[(c0 + 9) * DD + d]);
            B2f[(kt * 8 + nt) * 32 + lane] = make_uint2(b0, b1);
        }
    __syncthreads();
    // ==== no block syncs below — warps autonomous ====

    // ---- z: warp owns 32 rows = 2 MMA tiles; per thread 4 row-slots x 16 cols
    //      col(j) = 8*(j>>1) + 2*m + (j&1)
    const size_t rbase = (size_t)blockIdx.x * ROWS + wid * 32 + g;
    float zA0[16], zA1[16], zB0[16], zB1[16];
    #pragma unroll
    for (int blk = 0; blk < 8; blk++) {
        float2 v;
        v = *(const float2*)(z_in + (rbase     ) * DD + 8 * blk + 2 * m); zA0[2*blk]=v.x; zA0[2*blk+1]=v.y;
        v = *(const float2*)(z_in + (rbase +  8) * DD + 8 * blk + 2 * m); zA1[2*blk]=v.x; zA1[2*blk+1]=v.y;
        v = *(const float2*)(z_in + (rbase + 16) * DD + 8 * blk + 2 * m); zB0[2*blk]=v.x; zB0[2*blk+1]=v.y;
        v = *(const float2*)(z_in + (rbase + 24) * DD + 8 * blk + 2 * m); zB1[2*blk]=v.x; zB1[2*blk+1]=v.y;
    }

    #pragma unroll 1
    for (int step = 0; step < NSTEP; step++) {
        // ---- |z|^2 per row ----
        float sA0 = 0.f, sA1 = 0.f, sB0 = 0.f, sB1 = 0.f;
        #pragma unroll
        for (int j = 0; j < 16; j++) {
            sA0 = fmaf(zA0[j], zA0[j], sA0);
            sA1 = fmaf(zA1[j], zA1[j], sA1);
            sB0 = fmaf(zB0[j], zB0[j], sB0);
            sB1 = fmaf(zB1[j], zB1[j], sB1);
        }
        sA0 = qred(sA0); sA1 = qred(sA1); sB0 = qred(sB0); sB1 = qred(sB1);

        // ---- A fragments of GEMM1 (stored; 32 regs) ----
        uint32_t afA[4][4], afB[4][4];
        #pragma unroll
        for (int kt = 0; kt < 4; kt++) {
            afA[kt][0] = pack_bf16x2(zA0[4*kt+0], zA0[4*kt+1]);
            afA[kt][1] = pack_bf16x2(zA1[4*kt+0], zA1[4*kt+1]);
            afA[kt][2] = pack_bf16x2(zA0[4*kt+2], zA0[4*kt+3]);
            afA[kt][3] = pack_bf16x2(zA1[4*kt+2], zA1[4*kt+3]);
            afB[kt][0] = pack_bf16x2(zB0[4*kt+0], zB0[4*kt+1]);
            afB[kt][1] = pack_bf16x2(zB1[4*kt+0], zB1[4*kt+1]);
            afB[kt][2] = pack_bf16x2(zB0[4*kt+2], zB0[4*kt+3]);
            afB[kt][3] = pack_bf16x2(zB1[4*kt+2], zB1[4*kt+3]);
        }

        float gA[8][4], gB[8][4];
        #pragma unroll
        for (int i = 0; i < 8; i++) {
            gA[i][0]=gA[i][1]=gA[i][2]=gA[i][3]=0.f;
            gB[i][0]=gB[i][1]=gB[i][2]=gB[i][3]=0.f;
        }
        float naA0=0.f, naA1=0.f, naB0=0.f, naB1=0.f;
        float swA0=0.f, swA1=0.f, swB0=0.f, swB1=0.f;

        // ---- fused: per 16-center chunk KT, GEMM1 -> epilogue -> GEMM2 partial ----
        #pragma unroll 2
        for (int KT = 0; KT < 16; KT++) {
            float aA[2][4], aB[2][4];
            #pragma unroll
            for (int i = 0; i < 2; i++) {
                aA[i][0]=aA[i][1]=aA[i][2]=aA[i][3]=0.f;
                aB[i][0]=aB[i][1]=aB[i][2]=aB[i][3]=0.f;
            }
            #pragma unroll
            for (int kt = 0; kt < 4; kt++) {
                uint2 b0 = B1f[(kt * 32 + 2 * KT    ) * 32 + lane];
                uint2 b1 = B1f[(kt * 32 + 2 * KT + 1) * 32 + lane];
                mma16816(aA[0], afA[kt][0], afA[kt][1], afA[kt][2], afA[kt][3], b0.x, b0.y);
                mma16816(aB[0], afB[kt][0], afB[kt][1], afB[kt][2], afB[kt][3], b0.x, b0.y);
                mma16816(aA[1], afA[kt][0], afA[kt][1], afA[kt][2], afA[kt][3], b1.x, b1.y);
                mma16816(aB[1], afB[kt][0], afB[kt][1], afB[kt][2], afB[kt][3], b1.x, b1.y);
            }

            // epilogue: w = mu / r^3 over 16 centers (cols 16KT..16KT+15)
            const int c0 = 16 * KT + 2 * m;
            float2 q0 = sqm[c0], q1 = sqm[c0 + 1], q2 = sqm[c0 + 8], q3 = sqm[c0 + 9];
            uint32_t waA[4], waB[4];
            #pragma unroll
            for (int half = 0; half < 2; half++) {           // half 0: ntl even; 1: odd
                float2 p0 = half ? q2 : q0;
                float2 p1 = half ? q3 : q1;
                // tile A
                {
                    float t0 = fmaxf(fmaf(-2.f, aA[half][0], sA0 + p0.x), 0.f) + EPSV;
                    float t1 = fmaxf(fmaf(-2.f, aA[half][1], sA0 + p1.x), 0.f) + EPSV;
                    float t2 = fmaxf(fmaf(-2.f, aA[half][2], sA1 + p0.x), 0.f) + EPSV;
                    float t3 = fmaxf(fmaf(-2.f, aA[half][3], sA1 + p1.x), 0.f) + EPSV;
                    float i0 = rsqrtf(t0), i1 = rsqrtf(t1), i2 = rsqrtf(t2), i3 = rsqrtf(t3);
                    float m0 = p0.y*i0, m1 = p1.y*i1, m2 = p0.y*i2, m3 = p1.y*i3;
                    naA0 += m0 + m1;  naA1 += m2 + m3;
                    float w0 = m0*i0*i0, w1 = m1*i1*i1, w2 = m2*i2*i2, w3 = m3*i3*i3;
                    swA0 += w0 + w1;  swA1 += w2 + w3;
                    waA[2*half]     = pack_bf16x2(w0, w1);
                    waA[2*half + 1] = pack_bf16x2(w2, w3);
                }
                // tile B
                {
                    float t0 = fmaxf(fmaf(-2.f, aB[half][0], sB0 + p0.x), 0.f) + EPSV;
                    float t1 = fmaxf(fmaf(-2.f, aB[half][1], sB0 + p1.x), 0.f) + EPSV;
                    float t2 = fmaxf(fmaf(-2.f, aB[half][2], sB1 + p0.x), 0.f) + EPSV;
                    float t3 = fmaxf(fmaf(-2.f, aB[half][3], sB1 + p1.x), 0.f) + EPSV;
                    float i0 = rsqrtf(t0), i1 = rsqrtf(t1), i2 = rsqrtf(t2), i3 = rsqrtf(t3);
                    float m0 = p0.y*i0, m1 = p1.y*i1, m2 = p0.y*i2, m3 = p1.y*i3;
                    naB0 += m0 + m1;  naB1 += m2 + m3;
                    float w0 = m0*i0*i0, w1 = m1*i1*i1, w2 = m2*i2*i2, w3 = m3*i3*i3;
                    swB0 += w0 + w1;  swB1 += w2 + w3;
                    waB[2*half]     = pack_bf16x2(w0, w1);
                    waB[2*half + 1] = pack_bf16x2(w2, w3);
                }
            }
            // NOTE: wa[0]=row g cols 2m..2m+1 of this 16-k chunk; wa[1]=row g+8;
            //       wa[2],wa[3] = cols +8 — exactly the m16n8k16 A layout.

            // GEMM2 partial: G += W_chunk @ centers[16KT..16KT+16)
            #pragma unroll
            for (int nt = 0; nt < 8; nt++) {
                uint2 b = B2f[(KT * 8 + nt) * 32 + lane];
                mma16816(gA[nt], waA[0], waA[1], waA[2], waA[3], b.x, b.y);
                mma16816(gB[nt], waB[0], waB[1], waB[2], waB[3], b.x, b.y);
            }
        }

        // ---- row reductions + update ----
        naA0 = qred(naA0); naA1 = qred(naA1); naB0 = qred(naB0); naB1 = qred(naB1);
        swA0 = qred(swA0); swA1 = qred(swA1); swB0 = qred(swB0); swB1 = qred(swB1);
        const float cA0 = DTB / (1.f + naA0);
        const float cA1 = DTB / (1.f + naA1);
        const float cB0 = DTB / (1.f + naB0);
        const float cB1 = DTB / (1.f + naB1);
        #pragma unroll
        for (int nt = 0; nt < 8; nt++) {
            float u;
            u = fmaf(cA0, fmaf(-swA0, zA0[2*nt],   gA[nt][0]), zA0[2*nt]);   zA0[2*nt]   = fminf(fmaxf(u,-3.f),3.f);
            u = fmaf(cA0, fmaf(-swA0, zA0[2*nt+1], gA[nt][1]), zA0[2*nt+1]); zA0[2*nt+1] = fminf(fmaxf(u,-3.f),3.f);
            u = fmaf(cA1, fmaf(-swA1, zA1[2*nt],   gA[nt][2]), zA1[2*nt]);   zA1[2*nt]   = fminf(fmaxf(u,-3.f),3.f);
            u = fmaf(cA1, fmaf(-swA1, zA1[2*nt+1], gA[nt][3]), zA1[2*nt+1]); zA1[2*nt+1] = fminf(fmaxf(u,-3.f),3.f);
            u = fmaf(cB0, fmaf(-swB0, zB0[2*nt],   gB[nt][0]), zB0[2*nt]);   zB0[2*nt]   = fminf(fmaxf(u,-3.f),3.f);
            u = fmaf(cB0, fmaf(-swB0, zB0[2*nt+1], gB[nt][1]), zB0[2*nt+1]); zB0[2*nt+1] = fminf(fmaxf(u,-3.f),3.f);
            u = fmaf(cB1, fmaf(-swB1, zB1[2*nt],   gB[nt][2]), zB1[2*nt]);   zB1[2*nt]   = fminf(fmaxf(u,-3.f),3.f);
            u = fmaf(cB1, fmaf(-swB1, zB1[2*nt+1], gB[nt][3]), zB1[2*nt+1]); zB1[2*nt+1] = fminf(fmaxf(u,-3.f),3.f);
        }
    }

    // ---- store ----
    #pragma unroll
    for (int blk = 0; blk < 8; blk++) {
        *(float2*)(out + (rbase     ) * DD + 8*blk + 2*m) = make_float2(zA0[2*blk], zA0[2*blk+1]);
        *(float2*)(out + (rbase +  8) * DD + 8*blk + 2*m) = make_float2(zA1[2*blk], zA1[2*blk+1]);
        *(float2*)(out + (rbase + 16) * DD + 8*blk + 2*m) = make_float2(zB0[2*blk], zB0[2*blk+1]);
        *(float2*)(out + (rbase + 24) * DD + 8*blk + 2*m) = make_float2(zB1[2*blk], zB1[2*blk+1]);
    }
}

extern "C" void kernel_launch(void* const* d_in, const int* in_sizes, int n_in,
                              void* d_out, int out_size) {
    (void)in_sizes; (void)n_in; (void)out_size;
    const float* z       = (const float*)d_in[0];
    const float* centers = (const float*)d_in[1];
    const float* mus     = (const float*)d_in[2];
    float* out           = (float*)d_out;

    static bool attr_set = false;
    if (!attr_set) {
        cudaFuncSetAttribute(pm_field_mma_kernel,
                             cudaFuncAttributeMaxDynamicSharedMemorySize, SM_TOTAL);
        attr_set = true;
    }
    pm_field_mma_kernel<<<NBLK, THREADS, SM_TOTAL>>>(z, centers, mus, out);
}

// round 9
// speedup vs baseline: 6.4871x; 1.4076x over previous
#include <cuda_runtime.h>
#include <cuda_bf16.h>
#include <cstdint>

#define BB 131072
#define CC 256
#define DD 64
#define NSTEP 8
#define DTB 0.15f
#define EPSV 1e-4f
#define ROWS 128                  // per CTA (8 warps x 16 rows)
#define THREADS 256
#define NBLK (BB / ROWS)          // 1024

// ---------------- SMEM layout ----------------
// B1q: uint4[32 nt][2 ktp][32 lane]  GEMM1 B frags (kt pairs)  32768
// B2q: uint4[16 KT][4 ntp][32 lane]  GEMM2 B frags (nt pairs)  32768
// sqm: float2[256] (cn2, mu)                                    2048
#define SM_B1Q 0
#define SM_B2Q 32768
#define SM_QM  65536
#define SM_TOTAL 67584

static __device__ __forceinline__ uint32_t pack_bf16x2(float a, float b) {
    uint32_t r;
    asm("cvt.rn.bf16x2.f32 %0, %1, %2;" : "=r"(r) : "f"(b), "f"(a));
    return r;
}
static __device__ __forceinline__ void mma16816(
    float* c, uint32_t a0, uint32_t a1, uint32_t a2, uint32_t a3,
    uint32_t b0, uint32_t b1)
{
    asm volatile(
        "mma.sync.aligned.m16n8k16.row.col.f32.bf16.bf16.f32 "
        "{%0,%1,%2,%3}, {%4,%5,%6,%7}, {%8,%9}, {%0,%1,%2,%3};"
        : "+f"(c[0]), "+f"(c[1]), "+f"(c[2]), "+f"(c[3])
        : "r"(a0), "r"(a1), "r"(a2), "r"(a3), "r"(b0), "r"(b1));
}
static __device__ __forceinline__ float qred(float v) {
    v += __shfl_xor_sync(0xFFFFFFFFu, v, 1);
    v += __shfl_xor_sync(0xFFFFFFFFu, v, 2);
    return v;
}

__global__ void __launch_bounds__(THREADS, 2) pm_field_mma_kernel(
    const float* __restrict__ z_in,
    const float* __restrict__ centers,
    const float* __restrict__ mus,
    float* __restrict__ out)
{
    extern __shared__ char smem[];
    uint4*  B1q = (uint4*)(smem + SM_B1Q);
    uint4*  B2q = (uint4*)(smem + SM_B2Q);
    float2* sqm = (float2*)(smem + SM_QM);

    const int tid  = threadIdx.x;
    const int wid  = tid >> 5;
    const int lane = tid & 31;
    const int m    = lane & 3;
    const int g    = lane >> 2;

    // ---- setup: fragments straight from gmem (L2-resident, one-time) ----
    // B1q: warp w builds nt in [4w, 4w+4)
    for (int nt = 4 * wid; nt < 4 * wid + 4; nt++) {
        const float* p = centers + (8 * nt + g) * DD;
        #pragma unroll
        for (int ktp = 0; ktp < 2; ktp++) {
            const int d0 = 32 * ktp + 2 * m;
            float2 f0 = *(const float2*)(p + d0);
            float2 f1 = *(const float2*)(p + d0 + 8);
            float2 f2 = *(const float2*)(p + d0 + 16);
            float2 f3 = *(const float2*)(p + d0 + 24);
            uint4 v;
            v.x = pack_bf16x2(f0.x, f0.y);
            v.y = pack_bf16x2(f1.x, f1.y);
            v.z = pack_bf16x2(f2.x, f2.y);
            v.w = pack_bf16x2(f3.x, f3.y);
            B1q[(nt * 2 + ktp) * 32 + lane] = v;
        }
    }
    // B2q: warp w builds KT in {2w, 2w+1}
    for (int KT = 2 * wid; KT < 2 * wid + 2; KT++) {
        const int c0 = 16 * KT + 2 * m;
        #pragma unroll
        for (int ntp = 0; ntp < 4; ntp++) {
            const int d0 = 16 * ntp + g;
            uint4 v;
            v.x = pack_bf16x2(centers[(c0    ) * DD + d0], centers[(c0 + 1) * DD + d0]);
            v.y = pack_bf16x2(centers[(c0 + 8) * DD + d0], centers[(c0 + 9) * DD + d0]);
            v.z = pack_bf16x2(centers[(c0    ) * DD + d0 + 8], centers[(c0 + 1) * DD + d0 + 8]);
            v.w = pack_bf16x2(centers[(c0 + 8) * DD + d0 + 8], centers[(c0 + 9) * DD + d0 + 8]);
            B2q[(KT * 4 + ntp) * 32 + lane] = v;
        }
    }
    // cn2 + mu (one center per thread)
    {
        const int c = tid;   // THREADS == CC
        const float4* cr = (const float4*)(centers + c * DD);
        float s = 0.f;
        #pragma unroll
        for (int i = 0; i < DD / 4; i++) {
            float4 v = cr[i];
            s = fmaf(v.x, v.x, fmaf(v.y, v.y, fmaf(v.z, v.z, fmaf(v.w, v.w, s))));
        }
        sqm[c] = make_float2(s, mus[c]);
    }
    __syncthreads();
    // ==== no block syncs below — warps autonomous ====

    // ---- z: warp owns 16 rows (one MMA tile); thread: rows g, g+8; cols
    //      col(j) = 8*(j>>1) + 2*m + (j&1)
    const size_t rbase = (size_t)blockIdx.x * ROWS + wid * 16 + g;
    float z0[16], z1[16];
    #pragma unroll
    for (int blk = 0; blk < 8; blk++) {
        float2 v;
        v = *(const float2*)(z_in + (rbase    ) * DD + 8 * blk + 2 * m); z0[2*blk]=v.x; z0[2*blk+1]=v.y;
        v = *(const float2*)(z_in + (rbase + 8) * DD + 8 * blk + 2 * m); z1[2*blk]=v.x; z1[2*blk+1]=v.y;
    }

    #pragma unroll 1
    for (int step = 0; step < NSTEP; step++) {
        // |z|^2 per row
        float s0 = 0.f, s1 = 0.f;
        #pragma unroll
        for (int j = 0; j < 16; j++) {
            s0 = fmaf(z0[j], z0[j], s0);
            s1 = fmaf(z1[j], z1[j], s1);
        }
        s0 = qred(s0); s1 = qred(s1);

        // A fragments of GEMM1
        uint32_t af[4][4];
        #pragma unroll
        for (int kt = 0; kt < 4; kt++) {
            af[kt][0] = pack_bf16x2(z0[4*kt+0], z0[4*kt+1]);
            af[kt][1] = pack_bf16x2(z1[4*kt+0], z1[4*kt+1]);
            af[kt][2] = pack_bf16x2(z0[4*kt+2], z0[4*kt+3]);
            af[kt][3] = pack_bf16x2(z1[4*kt+2], z1[4*kt+3]);
        }

        float gacc[8][4];
        #pragma unroll
        for (int i = 0; i < 8; i++)
            gacc[i][0] = gacc[i][1] = gacc[i][2] = gacc[i][3] = 0.f;
        float na0 = 0.f, na1 = 0.f, sw0 = 0.f, sw1 = 0.f;

        // fused: per 16-center chunk: GEMM1 -> epilogue -> GEMM2 partial
        #pragma unroll 2
        for (int KT = 0; KT < 16; KT++) {
            float aA[2][4];
            #pragma unroll
            for (int i = 0; i < 2; i++)
                aA[i][0] = aA[i][1] = aA[i][2] = aA[i][3] = 0.f;

            {   // GEMM1: nt0 = 2KT (-> aA[0]), nt1 = 2KT+1 (-> aA[1]); kt pairs via LDS.128
                uint4 u0a = B1q[((2 * KT    ) * 2 + 0) * 32 + lane];
                uint4 u0b = B1q[((2 * KT    ) * 2 + 1) * 32 + lane];
                uint4 u1a = B1q[((2 * KT + 1) * 2 + 0) * 32 + lane];
                uint4 u1b = B1q[((2 * KT + 1) * 2 + 1) * 32 + lane];
                mma16816(aA[0], af[0][0], af[0][1], af[0][2], af[0][3], u0a.x, u0a.y);
                mma16816(aA[1], af[0][0], af[0][1], af[0][2], af[0][3], u1a.x, u1a.y);
                mma16816(aA[0], af[1][0], af[1][1], af[1][2], af[1][3], u0a.z, u0a.w);
                mma16816(aA[1], af[1][0], af[1][1], af[1][2], af[1][3], u1a.z, u1a.w);
                mma16816(aA[0], af[2][0], af[2][1], af[2][2], af[2][3], u0b.x, u0b.y);
                mma16816(aA[1], af[2][0], af[2][1], af[2][2], af[2][3], u1b.x, u1b.y);
                mma16816(aA[0], af[3][0], af[3][1], af[3][2], af[3][3], u0b.z, u0b.w);
                mma16816(aA[1], af[3][0], af[3][1], af[3][2], af[3][3], u1b.z, u1b.w);
            }

            // epilogue: w = mu / r^3 over cols 16KT..16KT+15
            const int c0 = 16 * KT + 2 * m;
            float2 q0 = sqm[c0], q1 = sqm[c0 + 1], q2 = sqm[c0 + 8], q3 = sqm[c0 + 9];
            uint32_t wa[4];
            #pragma unroll
            for (int half = 0; half < 2; half++) {
                float2 p0 = half ? q2 : q0;
                float2 p1 = half ? q3 : q1;
                float t0 = fmaxf(fmaf(-2.f, aA[half][0], s0 + p0.x), 0.f) + EPSV;
                float t1 = fmaxf(fmaf(-2.f, aA[half][1], s0 + p1.x), 0.f) + EPSV;
                float t2 = fmaxf(fmaf(-2.f, aA[half][2], s1 + p0.x), 0.f) + EPSV;
                float t3 = fmaxf(fmaf(-2.f, aA[half][3], s1 + p1.x), 0.f) + EPSV;
                float i0 = rsqrtf(t0), i1 = rsqrtf(t1), i2 = rsqrtf(t2), i3 = rsqrtf(t3);
                float m0 = p0.y * i0, m1 = p1.y * i1, m2 = p0.y * i2, m3 = p1.y * i3;
                na0 += m0 + m1;  na1 += m2 + m3;
                float w0 = m0*i0*i0, w1 = m1*i1*i1, w2 = m2*i2*i2, w3 = m3*i3*i3;
                sw0 += w0 + w1;  sw1 += w2 + w3;
                wa[2*half]     = pack_bf16x2(w0, w1);
                wa[2*half + 1] = pack_bf16x2(w2, w3);
            }

            // GEMM2 partial: nt pairs via LDS.128
            #pragma unroll
            for (int ntp = 0; ntp < 4; ntp++) {
                uint4 b = B2q[(KT * 4 + ntp) * 32 + lane];
                mma16816(gacc[2*ntp],     wa[0], wa[1], wa[2], wa[3], b.x, b.y);
                mma16816(gacc[2*ntp + 1], wa[0], wa[1], wa[2], wa[3], b.z, b.w);
            }
        }

        // row reductions + update
        na0 = qred(na0); na1 = qred(na1); sw0 = qred(sw0); sw1 = qred(sw1);
        const float c0f = DTB / (1.f + na0);
        const float c1f = DTB / (1.f + na1);
        #pragma unroll
        for (int nt = 0; nt < 8; nt++) {
            float u;
            u = fmaf(c0f, fmaf(-sw0, z0[2*nt],   gacc[nt][0]), z0[2*nt]);   z0[2*nt]   = fminf(fmaxf(u,-3.f),3.f);
            u = fmaf(c0f, fmaf(-sw0, z0[2*nt+1], gacc[nt][1]), z0[2*nt+1]); z0[2*nt+1] = fminf(fmaxf(u,-3.f),3.f);
            u = fmaf(c1f, fmaf(-sw1, z1[2*nt],   gacc[nt][2]), z1[2*nt]);   z1[2*nt]   = fminf(fmaxf(u,-3.f),3.f);
            u = fmaf(c1f, fmaf(-sw1, z1[2*nt+1], gacc[nt][3]), z1[2*nt+1]); z1[2*nt+1] = fminf(fmaxf(u,-3.f),3.f);
        }
    }

    // ---- store ----
    #pragma unroll
    for (int blk = 0; blk < 8; blk++) {
        *(float2*)(out + (rbase    ) * DD + 8*blk + 2*m) = make_float2(z0[2*blk], z0[2*blk+1]);
        *(float2*)(out + (rbase + 8) * DD + 8*blk + 2*m) = make_float2(z1[2*blk], z1[2*blk+1]);
    }
}

extern "C" void kernel_launch(void* const* d_in, const int* in_sizes, int n_in,
                              void* d_out, int out_size) {
    (void)in_sizes; (void)n_in; (void)out_size;
    const float* z       = (const float*)d_in[0];
    const float* centers = (const float*)d_in[1];
    const float* mus     = (const float*)d_in[2];
    float* out           = (float*)d_out;

    static bool attr_set = false;
    if (!attr_set) {
        cudaFuncSetAttribute(pm_field_mma_kernel,
                             cudaFuncAttributeMaxDynamicSharedMemorySize, SM_TOTAL);
        attr_set = true;
    }
    pm_field_mma_kernel<<<NBLK, THREADS, SM_TOTAL>>>(z, centers, mus, out);
}

// round 10
// speedup vs baseline: 6.9010x; 1.0638x over previous
#include <cuda_runtime.h>
#include <cuda_bf16.h>
#include <cstdint>

#define BB 131072
#define CC 256
#define DD 64
#define NSTEP 8
#define DTB 0.15f
#define EPSV 1e-4f
#define ROWS 128                  // per CTA (8 warps x 16 rows)
#define THREADS 256
#define NBLK (BB / ROWS)          // 1024

// ---------------- SMEM layout ----------------
// B1q: uint4[32 nt][2 ktp][32 lane]  GEMM1 B frags (kt pairs)  32768
// B2q: uint4[16 KT][4 ntp][32 lane]  GEMM2 B frags (nt pairs)  32768
// sqm: float2[256] = (cn2+eps, mu); adjacent pairs form float4  2048
#define SM_B1Q 0
#define SM_B2Q 32768
#define SM_QM  65536
#define SM_TOTAL 67584

static __device__ __forceinline__ uint32_t pack_bf16x2(float a, float b) {
    uint32_t r;
    asm("cvt.rn.bf16x2.f32 %0, %1, %2;" : "=r"(r) : "f"(b), "f"(a));
    return r;
}
static __device__ __forceinline__ void mma16816(
    float* c, uint32_t a0, uint32_t a1, uint32_t a2, uint32_t a3,
    uint32_t b0, uint32_t b1)
{
    asm volatile(
        "mma.sync.aligned.m16n8k16.row.col.f32.bf16.bf16.f32 "
        "{%0,%1,%2,%3}, {%4,%5,%6,%7}, {%8,%9}, {%0,%1,%2,%3};"
        : "+f"(c[0]), "+f"(c[1]), "+f"(c[2]), "+f"(c[3])
        : "r"(a0), "r"(a1), "r"(a2), "r"(a3), "r"(b0), "r"(b1));
}
static __device__ __forceinline__ float qred(float v) {
    v += __shfl_xor_sync(0xFFFFFFFFu, v, 1);
    v += __shfl_xor_sync(0xFFFFFFFFu, v, 2);
    return v;
}

__global__ void __launch_bounds__(THREADS, 2) pm_field_mma_kernel(
    const float* __restrict__ z_in,
    const float* __restrict__ centers,
    const float* __restrict__ mus,
    float* __restrict__ out)
{
    extern __shared__ char smem[];
    uint4* B1q = (uint4*)(smem + SM_B1Q);
    uint4* B2q = (uint4*)(smem + SM_B2Q);

    const int tid  = threadIdx.x;
    const int wid  = tid >> 5;
    const int lane = tid & 31;
    const int m    = lane & 3;
    const int g    = lane >> 2;

    // ---- setup: fragments straight from gmem (L2-resident, one-time) ----
    for (int nt = 4 * wid; nt < 4 * wid + 4; nt++) {
        const float* p = centers + (8 * nt + g) * DD;
        #pragma unroll
        for (int ktp = 0; ktp < 2; ktp++) {
            const int d0 = 32 * ktp + 2 * m;
            float2 f0 = *(const float2*)(p + d0);
            float2 f1 = *(const float2*)(p + d0 + 8);
            float2 f2 = *(const float2*)(p + d0 + 16);
            float2 f3 = *(const float2*)(p + d0 + 24);
            uint4 v;
            v.x = pack_bf16x2(f0.x, f0.y);
            v.y = pack_bf16x2(f1.x, f1.y);
            v.z = pack_bf16x2(f2.x, f2.y);
            v.w = pack_bf16x2(f3.x, f3.y);
            B1q[(nt * 2 + ktp) * 32 + lane] = v;
        }
    }
    for (int KT = 2 * wid; KT < 2 * wid + 2; KT++) {
        const int c0 = 16 * KT + 2 * m;
        #pragma unroll
        for (int ntp = 0; ntp < 4; ntp++) {
            const int d0 = 16 * ntp + g;
            uint4 v;
            v.x = pack_bf16x2(centers[(c0    ) * DD + d0], centers[(c0 + 1) * DD + d0]);
            v.y = pack_bf16x2(centers[(c0 + 8) * DD + d0], centers[(c0 + 9) * DD + d0]);
            v.z = pack_bf16x2(centers[(c0    ) * DD + d0 + 8], centers[(c0 + 1) * DD + d0 + 8]);
            v.w = pack_bf16x2(centers[(c0 + 8) * DD + d0 + 8], centers[(c0 + 9) * DD + d0 + 8]);
            B2q[(KT * 4 + ntp) * 32 + lane] = v;
        }
    }
    {   // (cn2+eps, mu) per center; adjacent pairs form an aligned float4
        const int c = tid;   // THREADS == CC
        const float4* cr = (const float4*)(centers + c * DD);
        float s = 0.f;
        #pragma unroll
        for (int i = 0; i < DD / 4; i++) {
            float4 v = cr[i];
            s = fmaf(v.x, v.x, fmaf(v.y, v.y, fmaf(v.z, v.z, fmaf(v.w, v.w, s))));
        }
        *(float2*)(smem + SM_QM + c * 8) = make_float2(s + EPSV, mus[c]);
    }
    __syncthreads();
    // ==== no block syncs below — warps autonomous ====

    const size_t rbase = (size_t)blockIdx.x * ROWS + wid * 16 + g;
    float z0[16], z1[16];
    #pragma unroll
    for (int blk = 0; blk < 8; blk++) {
        float2 v;
        v = *(const float2*)(z_in + (rbase    ) * DD + 8 * blk + 2 * m); z0[2*blk]=v.x; z0[2*blk+1]=v.y;
        v = *(const float2*)(z_in + (rbase + 8) * DD + 8 * blk + 2 * m); z1[2*blk]=v.x; z1[2*blk+1]=v.y;
    }

    #pragma unroll 1
    for (int step = 0; step < NSTEP; step++) {
        float s0 = 0.f, s1 = 0.f;
        #pragma unroll
        for (int j = 0; j < 16; j++) {
            s0 = fmaf(z0[j], z0[j], s0);
            s1 = fmaf(z1[j], z1[j], s1);
        }
        s0 = qred(s0); s1 = qred(s1);

        uint32_t af[4][4];
        #pragma unroll
        for (int kt = 0; kt < 4; kt++) {
            af[kt][0] = pack_bf16x2(z0[4*kt+0], z0[4*kt+1]);
            af[kt][1] = pack_bf16x2(z1[4*kt+0], z1[4*kt+1]);
            af[kt][2] = pack_bf16x2(z0[4*kt+2], z0[4*kt+3]);
            af[kt][3] = pack_bf16x2(z1[4*kt+2], z1[4*kt+3]);
        }

        float gacc[8][4];
        #pragma unroll
        for (int i = 0; i < 8; i++)
            gacc[i][0] = gacc[i][1] = gacc[i][2] = gacc[i][3] = 0.f;
        float na0 = 0.f, na1 = 0.f, sw0 = 0.f, sw1 = 0.f;

        #pragma unroll 2
        for (int KT = 0; KT < 16; KT++) {
            float aA[2][4];
            #pragma unroll
            for (int i = 0; i < 2; i++)
                aA[i][0] = aA[i][1] = aA[i][2] = aA[i][3] = 0.f;

            {   // GEMM1 (B via LDS.128, kt pairs)
                uint4 u0a = B1q[((2 * KT    ) * 2 + 0) * 32 + lane];
                uint4 u0b = B1q[((2 * KT    ) * 2 + 1) * 32 + lane];
                uint4 u1a = B1q[((2 * KT + 1) * 2 + 0) * 32 + lane];
                uint4 u1b = B1q[((2 * KT + 1) * 2 + 1) * 32 + lane];
                mma16816(aA[0], af[0][0], af[0][1], af[0][2], af[0][3], u0a.x, u0a.y);
                mma16816(aA[1], af[0][0], af[0][1], af[0][2], af[0][3], u1a.x, u1a.y);
                mma16816(aA[0], af[1][0], af[1][1], af[1][2], af[1][3], u0a.z, u0a.w);
                mma16816(aA[1], af[1][0], af[1][1], af[1][2], af[1][3], u1a.z, u1a.w);
                mma16816(aA[0], af[2][0], af[2][1], af[2][2], af[2][3], u0b.x, u0b.y);
                mma16816(aA[1], af[2][0], af[2][1], af[2][2], af[2][3], u1b.x, u1b.y);
                mma16816(aA[0], af[3][0], af[3][1], af[3][2], af[3][3], u0b.z, u0b.w);
                mma16816(aA[1], af[3][0], af[3][1], af[3][2], af[3][3], u1b.z, u1b.w);
            }

            // B2 loads issued BEFORE the epilogue: latency hides under rsqrt chain
            uint4 b2_0 = B2q[(KT * 4 + 0) * 32 + lane];
            uint4 b2_1 = B2q[(KT * 4 + 1) * 32 + lane];
            uint4 b2_2 = B2q[(KT * 4 + 2) * 32 + lane];
            uint4 b2_3 = B2q[(KT * 4 + 3) * 32 + lane];

            // (cn2+eps, mu) pairs: one broadcast LDS.128 per column pair
            const int c0 = 16 * KT + 2 * m;
            const float4 q01 = *(const float4*)(smem + SM_QM + c0 * 8);        // cols c0, c0+1
            const float4 q23 = *(const float4*)(smem + SM_QM + (c0 + 8) * 8);  // cols c0+8, c0+9

            uint32_t wa[4];
            #pragma unroll
            for (int half = 0; half < 2; half++) {
                const float4 P = half ? q23 : q01;   // (cn2e_lo, mu_lo, cn2e_hi, mu_hi)
                float t0 = fmaf(-2.f, aA[half][0], s0 + P.x);
                float t1 = fmaf(-2.f, aA[half][1], s0 + P.z);
                float t2 = fmaf(-2.f, aA[half][2], s1 + P.x);
                float t3 = fmaf(-2.f, aA[half][3], s1 + P.z);
                float i0 = rsqrtf(t0), i1 = rsqrtf(t1), i2 = rsqrtf(t2), i3 = rsqrtf(t3);
                float m0 = P.y * i0, m1 = P.w * i1, m2 = P.y * i2, m3 = P.w * i3;
                na0 += m0 + m1;  na1 += m2 + m3;
                float w0 = m0*i0*i0, w1 = m1*i1*i1, w2 = m2*i2*i2, w3 = m3*i3*i3;
                sw0 += w0 + w1;  sw1 += w2 + w3;
                wa[2*half]     = pack_bf16x2(w0, w1);
                wa[2*half + 1] = pack_bf16x2(w2, w3);
            }

            mma16816(gacc[0], wa[0], wa[1], wa[2], wa[3], b2_0.x, b2_0.y);
            mma16816(gacc[1], wa[0], wa[1], wa[2], wa[3], b2_0.z, b2_0.w);
            mma16816(gacc[2], wa[0], wa[1], wa[2], wa[3], b2_1.x, b2_1.y);
            mma16816(gacc[3], wa[0], wa[1], wa[2], wa[3], b2_1.z, b2_1.w);
            mma16816(gacc[4], wa[0], wa[1], wa[2], wa[3], b2_2.x, b2_2.y);
            mma16816(gacc[5], wa[0], wa[1], wa[2], wa[3], b2_2.z, b2_2.w);
            mma16816(gacc[6], wa[0], wa[1], wa[2], wa[3], b2_3.x, b2_3.y);
            mma16816(gacc[7], wa[0], wa[1], wa[2], wa[3], b2_3.z, b2_3.w);
        }

        na0 = qred(na0); na1 = qred(na1); sw0 = qred(sw0); sw1 = qred(sw1);
        const float c0f = DTB / (1.f + na0);
        const float c1f = DTB / (1.f + na1);
        #pragma unroll
        for (int nt = 0; nt < 8; nt++) {
            float u;
            u = fmaf(c0f, fmaf(-sw0, z0[2*nt],   gacc[nt][0]), z0[2*nt]);   z0[2*nt]   = fminf(fmaxf(u,-3.f),3.f);
            u = fmaf(c0f, fmaf(-sw0, z0[2*nt+1], gacc[nt][1]), z0[2*nt+1]); z0[2*nt+1] = fminf(fmaxf(u,-3.f),3.f);
            u = fmaf(c1f, fmaf(-sw1, z1[2*nt],   gacc[nt][2]), z1[2*nt]);   z1[2*nt]   = fminf(fmaxf(u,-3.f),3.f);
            u = fmaf(c1f, fmaf(-sw1, z1[2*nt+1], gacc[nt][3]), z1[2*nt+1]); z1[2*nt+1] = fminf(fmaxf(u,-3.f),3.f);
        }
    }

    #pragma unroll
    for (int blk = 0; blk < 8; blk++) {
        *(float2*)(out + (rbase    ) * DD + 8*blk + 2*m) = make_float2(z0[2*blk], z0[2*blk+1]);
        *(float2*)(out + (rbase + 8) * DD + 8*blk + 2*m) = make_float2(z1[2*blk], z1[2*blk+1]);
    }
}

extern "C" void kernel_launch(void* const* d_in, const int* in_sizes, int n_in,
                              void* d_out, int out_size) {
    (void)in_sizes; (void)n_in; (void)out_size;
    const float* z       = (const float*)d_in[0];
    const float* centers = (const float*)d_in[1];
    const float* mus     = (const float*)d_in[2];
    float* out           = (float*)d_out;

    static bool attr_set = false;
    if (!attr_set) {
        cudaFuncSetAttribute(pm_field_mma_kernel,
                             cudaFuncAttributeMaxDynamicSharedMemorySize, SM_TOTAL);
        attr_set = true;
    }
    pm_field_mma_kernel<<<NBLK, THREADS, SM_TOTAL>>>(z, centers, mus, out);
}

// round 11
// speedup vs baseline: 6.9644x; 1.0092x over previous
#include <cuda_runtime.h>
#include <cuda_bf16.h>
#include <cstdint>

#define BB 131072
#define CC 256
#define DD 64
#define NSTEP 8
#define DTB 0.15f
#define EPSV 1e-4f
#define ROWS 128                  // per CTA (8 warps x 16 rows)
#define THREADS 256
#define NBLK (BB / ROWS)          // 1024

// ---------------- SMEM layout ----------------
#define SM_B1Q 0                  // uint4[32 nt][2 ktp][32 lane]  32768
#define SM_B2Q 32768              // uint4[16 KT][4 ntp][32 lane]  32768
#define SM_QM  65536              // float2[256] = (cn2+eps, mu)    2048
#define SM_TOTAL 67584

static __device__ __forceinline__ uint32_t pack_bf16x2(float a, float b) {
    uint32_t r;
    asm("cvt.rn.bf16x2.f32 %0, %1, %2;" : "=r"(r) : "f"(b), "f"(a));
    return r;
}
static __device__ __forceinline__ void mma16816(
    float* c, uint32_t a0, uint32_t a1, uint32_t a2, uint32_t a3,
    uint32_t b0, uint32_t b1)
{
    asm volatile(
        "mma.sync.aligned.m16n8k16.row.col.f32.bf16.bf16.f32 "
        "{%0,%1,%2,%3}, {%4,%5,%6,%7}, {%8,%9}, {%0,%1,%2,%3};"
        : "+f"(c[0]), "+f"(c[1]), "+f"(c[2]), "+f"(c[3])
        : "r"(a0), "r"(a1), "r"(a2), "r"(a3), "r"(b0), "r"(b1));
}
static __device__ __forceinline__ float qred(float v) {
    v += __shfl_xor_sync(0xFFFFFFFFu, v, 1);
    v += __shfl_xor_sync(0xFFFFFFFFu, v, 2);
    return v;
}

__global__ void __launch_bounds__(THREADS, 2) pm_field_mma_kernel(
    const float* __restrict__ z_in,
    const float* __restrict__ centers,
    const float* __restrict__ mus,
    float* __restrict__ out)
{
    extern __shared__ char smem[];
    uint4* B1q = (uint4*)(smem + SM_B1Q);
    uint4* B2q = (uint4*)(smem + SM_B2Q);

    const int tid  = threadIdx.x;
    const int wid  = tid >> 5;
    const int lane = tid & 31;
    const int m    = lane & 3;
    const int g    = lane >> 2;

    // ---- setup: fragments straight from gmem ----
    for (int nt = 4 * wid; nt < 4 * wid + 4; nt++) {
        const float* p = centers + (8 * nt + g) * DD;
        #pragma unroll
        for (int ktp = 0; ktp < 2; ktp++) {
            const int d0 = 32 * ktp + 2 * m;
            float2 f0 = *(const float2*)(p + d0);
            float2 f1 = *(const float2*)(p + d0 + 8);
            float2 f2 = *(const float2*)(p + d0 + 16);
            float2 f3 = *(const float2*)(p + d0 + 24);
            uint4 v;
            v.x = pack_bf16x2(f0.x, f0.y);
            v.y = pack_bf16x2(f1.x, f1.y);
            v.z = pack_bf16x2(f2.x, f2.y);
            v.w = pack_bf16x2(f3.x, f3.y);
            B1q[(nt * 2 + ktp) * 32 + lane] = v;
        }
    }
    for (int KT = 2 * wid; KT < 2 * wid + 2; KT++) {
        const int c0 = 16 * KT + 2 * m;
        #pragma unroll
        for (int ntp = 0; ntp < 4; ntp++) {
            const int d0 = 16 * ntp + g;
            uint4 v;
            v.x = pack_bf16x2(centers[(c0    ) * DD + d0], centers[(c0 + 1) * DD + d0]);
            v.y = pack_bf16x2(centers[(c0 + 8) * DD + d0], centers[(c0 + 9) * DD + d0]);
            v.z = pack_bf16x2(centers[(c0    ) * DD + d0 + 8], centers[(c0 + 1) * DD + d0 + 8]);
            v.w = pack_bf16x2(centers[(c0 + 8) * DD + d0 + 8], centers[(c0 + 9) * DD + d0 + 8]);
            B2q[(KT * 4 + ntp) * 32 + lane] = v;
        }
    }
    {
        const int c = tid;   // THREADS == CC
        const float4* cr = (const float4*)(centers + c * DD);
        float s = 0.f;
        #pragma unroll
        for (int i = 0; i < DD / 4; i++) {
            float4 v = cr[i];
            s = fmaf(v.x, v.x, fmaf(v.y, v.y, fmaf(v.z, v.z, fmaf(v.w, v.w, s))));
        }
        *(float2*)(smem + SM_QM + c * 8) = make_float2(s + EPSV, mus[c]);
    }
    __syncthreads();
    // ==== no block syncs below — warps autonomous ====

    const size_t rbase = (size_t)blockIdx.x * ROWS + wid * 16 + g;
    float z0[16], z1[16];
    #pragma unroll
    for (int blk = 0; blk < 8; blk++) {
        float2 v;
        v = *(const float2*)(z_in + (rbase    ) * DD + 8 * blk + 2 * m); z0[2*blk]=v.x; z0[2*blk+1]=v.y;
        v = *(const float2*)(z_in + (rbase + 8) * DD + 8 * blk + 2 * m); z1[2*blk]=v.x; z1[2*blk+1]=v.y;
    }

    // constant ones B-fragment (column n=0): nonzero only on lanes with g==0
    const uint32_t bones = (g == 0) ? 0x3F803F80u : 0u;

    #pragma unroll 1
    for (int step = 0; step < NSTEP; step++) {
        float s0 = 0.f, s1 = 0.f;
        #pragma unroll
        for (int j = 0; j < 16; j++) {
            s0 = fmaf(z0[j], z0[j], s0);
            s1 = fmaf(z1[j], z1[j], s1);
        }
        s0 = qred(s0); s1 = qred(s1);

        uint32_t af[4][4];
        #pragma unroll
        for (int kt = 0; kt < 4; kt++) {
            af[kt][0] = pack_bf16x2(z0[4*kt+0], z0[4*kt+1]);
            af[kt][1] = pack_bf16x2(z1[4*kt+0], z1[4*kt+1]);
            af[kt][2] = pack_bf16x2(z0[4*kt+2], z0[4*kt+3]);
            af[kt][3] = pack_bf16x2(z1[4*kt+2], z1[4*kt+3]);
        }

        float gacc[8][4];
        #pragma unroll
        for (int i = 0; i < 8; i++)
            gacc[i][0] = gacc[i][1] = gacc[i][2] = gacc[i][3] = 0.f;
        float swacc[4] = {0.f, 0.f, 0.f, 0.f};   // Σw   via W @ ones
        float naacc[4] = {0.f, 0.f, 0.f, 0.f};   // Σm   via M @ ones

        #pragma unroll 2
        for (int KT = 0; KT < 16; KT++) {
            float aA[2][4];
            #pragma unroll
            for (int i = 0; i < 2; i++)
                aA[i][0] = aA[i][1] = aA[i][2] = aA[i][3] = 0.f;

            {   // GEMM1 (B via LDS.128, kt pairs)
                uint4 u0a = B1q[((2 * KT    ) * 2 + 0) * 32 + lane];
                uint4 u0b = B1q[((2 * KT    ) * 2 + 1) * 32 + lane];
                uint4 u1a = B1q[((2 * KT + 1) * 2 + 0) * 32 + lane];
                uint4 u1b = B1q[((2 * KT + 1) * 2 + 1) * 32 + lane];
                mma16816(aA[0], af[0][0], af[0][1], af[0][2], af[0][3], u0a.x, u0a.y);
                mma16816(aA[1], af[0][0], af[0][1], af[0][2], af[0][3], u1a.x, u1a.y);
                mma16816(aA[0], af[1][0], af[1][1], af[1][2], af[1][3], u0a.z, u0a.w);
                mma16816(aA[1], af[1][0], af[1][1], af[1][2], af[1][3], u1a.z, u1a.w);
                mma16816(aA[0], af[2][0], af[2][1], af[2][2], af[2][3], u0b.x, u0b.y);
                mma16816(aA[1], af[2][0], af[2][1], af[2][2], af[2][3], u1b.x, u1b.y);
                mma16816(aA[0], af[3][0], af[3][1], af[3][2], af[3][3], u0b.z, u0b.w);
                mma16816(aA[1], af[3][0], af[3][1], af[3][2], af[3][3], u1b.z, u1b.w);
            }

            // B2 prefetch before epilogue (latency hides under rsqrt chain)
            uint4 b2_0 = B2q[(KT * 4 + 0) * 32 + lane];
            uint4 b2_1 = B2q[(KT * 4 + 1) * 32 + lane];
            uint4 b2_2 = B2q[(KT * 4 + 2) * 32 + lane];
            uint4 b2_3 = B2q[(KT * 4 + 3) * 32 + lane];

            const int c0 = 16 * KT + 2 * m;
            const float4 q01 = *(const float4*)(smem + SM_QM + c0 * 8);
            const float4 q23 = *(const float4*)(smem + SM_QM + (c0 + 8) * 8);

            uint32_t wa[4], ma[4];
            #pragma unroll
            for (int half = 0; half < 2; half++) {
                const float4 P = half ? q23 : q01;   // (cn2e_lo, mu_lo, cn2e_hi, mu_hi)
                float t0 = fmaf(-2.f, aA[half][0], s0 + P.x);
                float t1 = fmaf(-2.f, aA[half][1], s0 + P.z);
                float t2 = fmaf(-2.f, aA[half][2], s1 + P.x);
                float t3 = fmaf(-2.f, aA[half][3], s1 + P.z);
                float i0 = rsqrtf(t0), i1 = rsqrtf(t1), i2 = rsqrtf(t2), i3 = rsqrtf(t3);
                float m0 = P.y * i0, m1 = P.w * i1, m2 = P.y * i2, m3 = P.w * i3;
                float w0 = m0*i0*i0, w1 = m1*i1*i1, w2 = m2*i2*i2, w3 = m3*i3*i3;
                wa[2*half]     = pack_bf16x2(w0, w1);
                wa[2*half + 1] = pack_bf16x2(w2, w3);
                ma[2*half]     = pack_bf16x2(m0, m1);
                ma[2*half + 1] = pack_bf16x2(m2, m3);
            }

            // sums on the tensor pipe: col 0 of (W|M) @ ones
            mma16816(swacc, wa[0], wa[1], wa[2], wa[3], bones, bones);
            mma16816(naacc, ma[0], ma[1], ma[2], ma[3], bones, bones);

            mma16816(gacc[0], wa[0], wa[1], wa[2], wa[3], b2_0.x, b2_0.y);
            mma16816(gacc[1], wa[0], wa[1], wa[2], wa[3], b2_0.z, b2_0.w);
            mma16816(gacc[2], wa[0], wa[1], wa[2], wa[3], b2_1.x, b2_1.y);
            mma16816(gacc[3], wa[0], wa[1], wa[2], wa[3], b2_1.z, b2_1.w);
            mma16816(gacc[4], wa[0], wa[1], wa[2], wa[3], b2_2.x, b2_2.y);
            mma16816(gacc[5], wa[0], wa[1], wa[2], wa[3], b2_2.z, b2_2.w);
            mma16816(gacc[6], wa[0], wa[1], wa[2], wa[3], b2_3.x, b2_3.y);
            mma16816(gacc[7], wa[0], wa[1], wa[2], wa[3], b2_3.z, b2_3.w);
        }

        // sums live in col 0 (lanes m==0): c[0]=row g, c[2]=row g+8 — broadcast in quad
        const int qbase = lane & 28;
        const float sw0 = __shfl_sync(0xFFFFFFFFu, swacc[0], qbase);
        const float sw1 = __shfl_sync(0xFFFFFFFFu, swacc[2], qbase);
        const float na0 = __shfl_sync(0xFFFFFFFFu, naacc[0], qbase);
        const float na1 = __shfl_sync(0xFFFFFFFFu, naacc[2], qbase);

        const float c0f = DTB / (1.f + na0);
        const float c1f = DTB / (1.f + na1);
        #pragma unroll
        for (int nt = 0; nt < 8; nt++) {
            float u;
            u = fmaf(c0f, fmaf(-sw0, z0[2*nt],   gacc[nt][0]), z0[2*nt]);   z0[2*nt]   = fminf(fmaxf(u,-3.f),3.f);
            u = fmaf(c0f, fmaf(-sw0, z0[2*nt+1], gacc[nt][1]), z0[2*nt+1]); z0[2*nt+1] = fminf(fmaxf(u,-3.f),3.f);
            u = fmaf(c1f, fmaf(-sw1, z1[2*nt],   gacc[nt][2]), z1[2*nt]);   z1[2*nt]   = fminf(fmaxf(u,-3.f),3.f);
            u = fmaf(c1f, fmaf(-sw1, z1[2*nt+1], gacc[nt][3]), z1[2*nt+1]); z1[2*nt+1] = fminf(fmaxf(u,-3.f),3.f);
        }
    }

    #pragma unroll
    for (int blk = 0; blk < 8; blk++) {
        *(float2*)(out + (rbase    ) * DD + 8*blk + 2*m) = make_float2(z0[2*blk], z0[2*blk+1]);
        *(float2*)(out + (rbase + 8) * DD + 8*blk + 2*m) = make_float2(z1[2*blk], z1[2*blk+1]);
    }
}

extern "C" void kernel_launch(void* const* d_in, const int* in_sizes, int n_in,
                              void* d_out, int out_size) {
    (void)in_sizes; (void)n_in; (void)out_size;
    const float* z       = (const float*)d_in[0];
    const float* centers = (const float*)d_in[1];
    const float* mus     = (const float*)d_in[2];
    float* out           = (float*)d_out;

    static bool attr_set = false;
    if (!attr_set) {
        cudaFuncSetAttribute(pm_field_mma_kernel,
                             cudaFuncAttributeMaxDynamicSharedMemorySize, SM_TOTAL);
        attr_set = true;
    }
    pm_field_mma_kernel<<<NBLK, THREADS, SM_TOTAL>>>(z, centers, mus, out);
}